// round 4
// baseline (speedup 1.0000x reference)
#include <cuda_runtime.h>
#include <cstdint>

// PS-ROI Align, two-phase, branchless predicated f32x2 inner loop.
//   Phase 1: per (roi, axis-pos) factorized 3-tap weights + clamped indices.
//   Phase 2: persistent single-wave grid (49 bins x 12 chunks). Bin slice
//   (51.2KB) in SMEM; each 8-lane group produces one (roi,bin) via
//   4 unconditional + 5 predicated LDS.128 (@p, no BSSY) + f32x2 FMAs.

namespace {
constexpr int POOLN       = 7;
constexpr int TOTAL_BINS  = 49;
constexpr int ALPHA       = 32;
constexpr int HH          = 20;
constexpr int WW          = 20;
constexpr int THREADS     = 256;
constexpr int GROUPS      = THREADS / 8;        // 32 rois per iter
constexpr int CHUNKS      = 12;                 // 49*12 = 588 blocks ~ 1 wave @ occ4
constexpr int MAX_ROIS    = 8192;
constexpr int SMEM_F4     = HH * WW * (ALPHA / 4);  // 3200 float4
constexpr int SMEM_BYTES  = SMEM_F4 * 16;           // 51200 B
}

// .x = bitcast int: i0 | i1<<8 | i2<<16 (clamped indices); .y/.z/.w = W0,W1,W2
__device__ float4 g_TX[MAX_ROIS * POOLN];
__device__ float4 g_TY[MAX_ROIS * POOLN];

__device__ __forceinline__ float4 axis_record(float origin, float step, int pos)
{
    const float sc = 19.0f / 20.0f;
    float c1 = (origin + (float)pos * step) * sc;
    float c2 = (origin + (float)(pos + 1) * step) * sc;

    float f1 = floorf(c1), f2 = floorf(c2);
    float w1 = c1 - f1,    w2 = c2 - f2;
    float v1 = (c1 >= 0.0f && c1 <= 19.0f) ? 1.0f : 0.0f;
    float v2 = (c2 >= 0.0f && c2 <= 19.0f) ? 1.0f : 0.0f;

    int a1 = min(max((int)f1, 0), 19);
    int b1 = min(a1 + 1, 19);
    int a2 = min(max((int)f2, 0), 19);
    int b2 = min(a2 + 1, 19);

    int o1 = b1 - a1;
    int o2 = min(max(a2 - a1, 0), 2);
    int o3 = min(max(b2 - a1, 0), 2);

    float u1 = v1 - v1 * w1;
    float u2 = v1 * w1;
    float u3 = v2 - v2 * w2;
    float u4 = v2 * w2;

    float W0 = u1 + (o1 == 0 ? u2 : 0.0f) + (o2 == 0 ? u3 : 0.0f) + (o3 == 0 ? u4 : 0.0f);
    float W1 =      (o1 == 1 ? u2 : 0.0f) + (o2 == 1 ? u3 : 0.0f) + (o3 == 1 ? u4 : 0.0f);
    float W2 =                              (o2 == 2 ? u3 : 0.0f) + (o3 == 2 ? u4 : 0.0f);

    int i0 = a1;
    int i1 = min(a1 + 1, 19);
    int i2 = min(a1 + 2, 19);

    float4 rec;
    rec.x = __int_as_float(i0 | (i1 << 8) | (i2 << 16));
    rec.y = W0; rec.z = W1; rec.w = W2;
    return rec;
}

__global__ void psroi_setup_kernel(const float4* __restrict__ rois4, int R)
{
    int idx = blockIdx.x * blockDim.x + threadIdx.x;   // roi*7 + pos
    if (idx >= R * POOLN) return;
    int roi = idx / POOLN;
    int pos = idx - roi * POOLN;
    float4 r = __ldg(&rois4[roi]);
    g_TX[idx] = axis_record(r.x, r.z * (1.0f / 7.0f), pos);
    g_TY[idx] = axis_record(r.y, r.w * (1.0f / 7.0f), pos);
}

// ---- packed f32x2 helpers ----
__device__ __forceinline__ unsigned long long pack2(float a) {
    unsigned long long r;
    asm("mov.b64 %0, {%1, %1};" : "=l"(r) : "f"(a));
    return r;
}
__device__ __forceinline__ unsigned long long mul2(unsigned long long a,
                                                   unsigned long long b) {
    unsigned long long r;
    asm("mul.rn.f32x2 %0, %1, %2;" : "=l"(r) : "l"(a), "l"(b));
    return r;
}
__device__ __forceinline__ void fma2(unsigned long long& d,
                                     unsigned long long a,
                                     unsigned long long b) {
    asm("fma.rn.f32x2 %0, %1, %2, %0;" : "+l"(d) : "l"(a), "l"(b));
}
__device__ __forceinline__ void lds128(unsigned long long& v0,
                                       unsigned long long& v1,
                                       uint32_t addr) {
    asm("ld.shared.v2.b64 {%0, %1}, [%2];" : "=l"(v0), "=l"(v1) : "r"(addr));
}
// Predicated LDS.128: inactive lanes produce zeros, generate no smem wavefronts,
// and (critically) no BSSY/BSYNC reconvergence overhead.
__device__ __forceinline__ void lds128_pred(unsigned long long& v0,
                                            unsigned long long& v1,
                                            uint32_t addr, uint32_t flag) {
    asm("{ .reg .pred p;\n\t"
        "setp.ne.u32 p, %2, 0;\n\t"
        "@!p mov.b64 %0, 0;\n\t"
        "@!p mov.b64 %1, 0;\n\t"
        "@p ld.shared.v2.b64 {%0, %1}, [%3]; }"
        : "=l"(v0), "=l"(v1) : "r"(flag), "r"(addr));
}

__global__ __launch_bounds__(THREADS, 4)
void psroi_main_kernel(const float4* __restrict__ img4,
                       ulonglong2* __restrict__ out2,
                       int R)
{
    extern __shared__ float4 s4[];     // [pix = y*20+x][aq 0..7]

    const int bin = blockIdx.x;        // 0..48
    const int bx  = bin / POOLN;
    const int by  = bin % POOLN;

    {   // stage this bin's slice (51.2KB) into SMEM
        const int binoff4 = bin * (ALPHA / 4);
        #pragma unroll 4
        for (int p = threadIdx.x; p < SMEM_F4; p += THREADS) {
            int pix = p >> 3;
            int aq  = p & 7;
            s4[p] = img4[pix * (TOTAL_BINS * ALPHA / 4) + binoff4 + aq];
        }
    }
    __syncthreads();

    const int grp = threadIdx.x >> 3;
    const int q   = threadIdx.x & 7;

    // persistent chunking: block y handles rois [begin, end)
    const int per_chunk = (R + CHUNKS - 1) / CHUNKS;     // 683
    const int roi_begin = blockIdx.y * per_chunk;
    const int roi_end   = min(roi_begin + per_chunk, R);
    const int iters     = (roi_end - roi_begin + GROUPS - 1) / GROUPS;

    const uint32_t sbase =
        (uint32_t)__cvta_generic_to_shared(s4) + (uint32_t)(q * 16);
    const unsigned long long quarter2 = pack2(0.25f);

    #pragma unroll 2
    for (int it = 0; it < iters; ++it) {
        const int roi = roi_begin + it * GROUPS + grp;
        const bool active = (roi < roi_end);
        const int ridx = active ? roi : (roi_end - 1);

        const float4 wx = __ldg(&g_TX[ridx * POOLN + bx]);
        const float4 wy = __ldg(&g_TY[ridx * POOLN + by]);

        const uint32_t px = (uint32_t)__float_as_int(wx.x);
        const uint32_t py = (uint32_t)__float_as_int(wy.x);
        const uint32_t c0 = sbase + ((px & 255u) << 7);
        const uint32_t c1 = sbase + (((px >> 8) & 255u) << 7);
        const uint32_t c2 = sbase + (((px >> 16) & 255u) << 7);
        const uint32_t r0 = (py & 255u) * 2560u;
        const uint32_t r1 = ((py >> 8) & 255u) * 2560u;
        const uint32_t r2 = ((py >> 16) & 255u) * 2560u;

        const uint32_t fx2 = (wx.w != 0.0f) ? 1u : 0u;
        const uint32_t fy2 = (wy.w != 0.0f) ? 1u : 0u;
        const uint32_t fxy = fx2 & fy2;

        const unsigned long long wx0 = pack2(wx.y);
        const unsigned long long wx1 = pack2(wx.z);
        const unsigned long long wx2 = pack2(wx.w);
        const unsigned long long wy0 = pack2(wy.y);
        const unsigned long long wy1 = pack2(wy.z);
        const unsigned long long wy2 = pack2(wy.w);

        unsigned long long a01 = 0ull, a23 = 0ull;

        #define SAMP(RW, CW, ADDR) do {                 \
            unsigned long long v0_, v1_;                \
            lds128(v0_, v1_, (ADDR));                   \
            unsigned long long w_ = mul2((RW), (CW));   \
            fma2(a01, w_, v0_);                         \
            fma2(a23, w_, v1_);                         \
        } while (0)

        #define SAMP_P(RW, CW, ADDR, FLAG) do {         \
            unsigned long long v0_, v1_;                \
            lds128_pred(v0_, v1_, (ADDR), (FLAG));      \
            unsigned long long w_ = mul2((RW), (CW));   \
            fma2(a01, w_, v0_);                         \
            fma2(a23, w_, v1_);                         \
        } while (0)

        SAMP(wy0, wx0, r0 + c0);
        SAMP(wy0, wx1, r0 + c1);
        SAMP(wy1, wx0, r1 + c0);
        SAMP(wy1, wx1, r1 + c1);
        SAMP_P(wy0, wx2, r0 + c2, fx2);
        SAMP_P(wy1, wx2, r1 + c2, fx2);
        SAMP_P(wy2, wx0, r2 + c0, fy2);
        SAMP_P(wy2, wx1, r2 + c1, fy2);
        SAMP_P(wy2, wx2, r2 + c2, fxy);
        #undef SAMP
        #undef SAMP_P

        a01 = mul2(a01, quarter2);
        a23 = mul2(a23, quarter2);

        if (active) {
            ulonglong2 o; o.x = a01; o.y = a23;
            out2[roi * (TOTAL_BINS * ALPHA / 4) + bin * (ALPHA / 4) + q] = o;
        }
    }
}

extern "C" void kernel_launch(void* const* d_in, const int* in_sizes, int n_in,
                              void* d_out, int out_size)
{
    const float* p0 = (const float*)d_in[0];
    const float* p1 = (const float*)d_in[1];
    const float* img  = p0;
    const float* rois = p1;
    int rois_elems = in_sizes[1];
    if (in_sizes[0] < in_sizes[1]) {
        img = p1; rois = p0; rois_elems = in_sizes[0];
    }
    const int R = rois_elems / 4;      // 8192

    {
        int total = R * POOLN;
        int blocks = (total + 255) / 256;
        psroi_setup_kernel<<<blocks, 256>>>((const float4*)rois, R);
    }

    cudaFuncSetAttribute(psroi_main_kernel,
                         cudaFuncAttributeMaxDynamicSharedMemorySize, SMEM_BYTES);
    dim3 grid(TOTAL_BINS, CHUNKS);     // 49 x 12 = 588 blocks: single wave
    psroi_main_kernel<<<grid, THREADS, SMEM_BYTES>>>(
        (const float4*)img, (ulonglong2*)d_out, R);
}

// round 5
// speedup vs baseline: 1.1100x; 1.1100x over previous
#include <cuda_runtime.h>
#include <cstdint>

// PS-ROI Align, two-phase. Round-3 skeleton (grid 49 x 32, 256 rois/block,
// occ 4) + cp.async staging + predicated zero-weight taps + 0.25 folded into
// the weight tables.

namespace {
constexpr int POOLN       = 7;
constexpr int TOTAL_BINS  = 49;
constexpr int ALPHA       = 32;
constexpr int HH          = 20;
constexpr int WW          = 20;
constexpr int THREADS     = 256;
constexpr int GROUPS      = THREADS / 8;        // 32 rois per iter
constexpr int ROIS_PER_BLOCK = 256;
constexpr int MAX_ROIS    = 8192;
constexpr int SMEM_F4     = HH * WW * (ALPHA / 4);  // 3200 float4
constexpr int SMEM_BYTES  = SMEM_F4 * 16;           // 51200 B
}

// .x = bitcast int: i0 | i1<<8 | i2<<16 (clamped indices); .y/.z/.w = W0,W1,W2
// Weights are pre-scaled by 0.5 per axis (product gives the 0.25 mean factor).
__device__ float4 g_TX[MAX_ROIS * POOLN];
__device__ float4 g_TY[MAX_ROIS * POOLN];

__device__ __forceinline__ float4 axis_record(float origin, float step, int pos)
{
    const float sc = 19.0f / 20.0f;
    float c1 = (origin + (float)pos * step) * sc;
    float c2 = (origin + (float)(pos + 1) * step) * sc;

    float f1 = floorf(c1), f2 = floorf(c2);
    float w1 = c1 - f1,    w2 = c2 - f2;
    float v1 = (c1 >= 0.0f && c1 <= 19.0f) ? 1.0f : 0.0f;
    float v2 = (c2 >= 0.0f && c2 <= 19.0f) ? 1.0f : 0.0f;

    int a1 = min(max((int)f1, 0), 19);
    int b1 = min(a1 + 1, 19);
    int a2 = min(max((int)f2, 0), 19);
    int b2 = min(a2 + 1, 19);

    int o1 = b1 - a1;
    int o2 = min(max(a2 - a1, 0), 2);
    int o3 = min(max(b2 - a1, 0), 2);

    float u1 = v1 - v1 * w1;
    float u2 = v1 * w1;
    float u3 = v2 - v2 * w2;
    float u4 = v2 * w2;

    float W0 = u1 + (o1 == 0 ? u2 : 0.0f) + (o2 == 0 ? u3 : 0.0f) + (o3 == 0 ? u4 : 0.0f);
    float W1 =      (o1 == 1 ? u2 : 0.0f) + (o2 == 1 ? u3 : 0.0f) + (o3 == 1 ? u4 : 0.0f);
    float W2 =                              (o2 == 2 ? u3 : 0.0f) + (o3 == 2 ? u4 : 0.0f);

    int i0 = a1;
    int i1 = min(a1 + 1, 19);
    int i2 = min(a1 + 2, 19);

    float4 rec;
    rec.x = __int_as_float(i0 | (i1 << 8) | (i2 << 16));
    rec.y = 0.5f * W0; rec.z = 0.5f * W1; rec.w = 0.5f * W2;
    return rec;
}

__global__ void psroi_setup_kernel(const float4* __restrict__ rois4, int R)
{
    int idx = blockIdx.x * blockDim.x + threadIdx.x;   // roi*7 + pos
    if (idx >= R * POOLN) return;
    int roi = idx / POOLN;
    int pos = idx - roi * POOLN;
    float4 r = __ldg(&rois4[roi]);
    g_TX[idx] = axis_record(r.x, r.z * (1.0f / 7.0f), pos);
    g_TY[idx] = axis_record(r.y, r.w * (1.0f / 7.0f), pos);
}

// ---- packed f32x2 helpers ----
__device__ __forceinline__ unsigned long long pack2(float a) {
    unsigned long long r;
    asm("mov.b64 %0, {%1, %1};" : "=l"(r) : "f"(a));
    return r;
}
__device__ __forceinline__ unsigned long long mul2(unsigned long long a,
                                                   unsigned long long b) {
    unsigned long long r;
    asm("mul.rn.f32x2 %0, %1, %2;" : "=l"(r) : "l"(a), "l"(b));
    return r;
}
__device__ __forceinline__ void fma2(unsigned long long& d,
                                     unsigned long long a,
                                     unsigned long long b) {
    asm("fma.rn.f32x2 %0, %1, %2, %0;" : "+l"(d) : "l"(a), "l"(b));
}
__device__ __forceinline__ void lds128(unsigned long long& v0,
                                       unsigned long long& v1,
                                       uint32_t addr) {
    asm("ld.shared.v2.b64 {%0, %1}, [%2];" : "=l"(v0), "=l"(v1) : "r"(addr));
}
// Predicated LDS.128: inactive groups produce zeros and no smem wavefronts,
// with no BSSY/BSYNC reconvergence.
__device__ __forceinline__ void lds128_pred(unsigned long long& v0,
                                            unsigned long long& v1,
                                            uint32_t addr, uint32_t flag) {
    asm("{ .reg .pred p;\n\t"
        "setp.ne.u32 p, %2, 0;\n\t"
        "@!p mov.b64 %0, 0;\n\t"
        "@!p mov.b64 %1, 0;\n\t"
        "@p ld.shared.v2.b64 {%0, %1}, [%3]; }"
        : "=l"(v0), "=l"(v1) : "r"(flag), "r"(addr));
}
// cp.async 16B: global -> shared without the register round-trip.
__device__ __forceinline__ void cpasync16(uint32_t dst, const void* src) {
    asm volatile("cp.async.cg.shared.global [%0], [%1], 16;"
                 :: "r"(dst), "l"(src));
}

__global__ __launch_bounds__(THREADS, 4)
void psroi_main_kernel(const float4* __restrict__ img4,
                       ulonglong2* __restrict__ out2)
{
    extern __shared__ float4 s4[];     // [pix = y*20+x][aq 0..7]

    const int bin = blockIdx.x;        // 0..48
    const int bx  = bin / POOLN;
    const int by  = bin % POOLN;

    const uint32_t smem0 = (uint32_t)__cvta_generic_to_shared(s4);

    {   // stage this bin's slice (51.2KB) into SMEM via cp.async
        const int binoff4 = bin * (ALPHA / 4);
        #pragma unroll
        for (int k = 0; k < SMEM_F4 / THREADS; ++k) {      // 12 full rounds
            int p = k * THREADS + threadIdx.x;
            int pix = p >> 3;
            int aq  = p & 7;
            cpasync16(smem0 + (uint32_t)p * 16u,
                      img4 + pix * (TOTAL_BINS * ALPHA / 4) + binoff4 + aq);
        }
        {   // remainder: 3200 = 12*256 + 128
            int p = (SMEM_F4 / THREADS) * THREADS + threadIdx.x;
            if (p < SMEM_F4) {
                int pix = p >> 3;
                int aq  = p & 7;
                cpasync16(smem0 + (uint32_t)p * 16u,
                          img4 + pix * (TOTAL_BINS * ALPHA / 4) + binoff4 + aq);
            }
        }
        asm volatile("cp.async.commit_group;");
        asm volatile("cp.async.wait_group 0;");
    }
    __syncthreads();

    const int grp = threadIdx.x >> 3;
    const int q   = threadIdx.x & 7;
    const int roi_base = blockIdx.y * ROIS_PER_BLOCK;

    const uint32_t sbase = smem0 + (uint32_t)(q * 16);

    int txi = (roi_base + grp) * POOLN + bx;
    int tyi = (roi_base + grp) * POOLN + by;

    #pragma unroll 2
    for (int it = 0; it < ROIS_PER_BLOCK / GROUPS; ++it) {
        const int roi = roi_base + it * GROUPS + grp;
        const float4 wx = __ldg(&g_TX[txi]);
        const float4 wy = __ldg(&g_TY[tyi]);
        txi += GROUPS * POOLN;
        tyi += GROUPS * POOLN;

        const uint32_t px = (uint32_t)__float_as_int(wx.x);
        const uint32_t py = (uint32_t)__float_as_int(wy.x);
        const uint32_t c0 = sbase + ((px & 255u) << 7);
        const uint32_t c1 = sbase + (((px >> 8) & 255u) << 7);
        const uint32_t c2 = sbase + (((px >> 16) & 255u) << 7);
        const uint32_t r0 = (py & 255u) * 2560u;
        const uint32_t r1 = ((py >> 8) & 255u) * 2560u;
        const uint32_t r2 = ((py >> 16) & 255u) * 2560u;

        const uint32_t fx2 = (wx.w != 0.0f) ? 1u : 0u;
        const uint32_t fy2 = (wy.w != 0.0f) ? 1u : 0u;
        const uint32_t fxy = fx2 & fy2;

        const unsigned long long wx0 = pack2(wx.y);
        const unsigned long long wx1 = pack2(wx.z);
        const unsigned long long wx2 = pack2(wx.w);
        const unsigned long long wy0 = pack2(wy.y);
        const unsigned long long wy1 = pack2(wy.z);
        const unsigned long long wy2 = pack2(wy.w);

        unsigned long long a01 = 0ull, a23 = 0ull;

        #define SAMP(RW, CW, ADDR) do {                 \
            unsigned long long v0_, v1_;                \
            lds128(v0_, v1_, (ADDR));                   \
            unsigned long long w_ = mul2((RW), (CW));   \
            fma2(a01, w_, v0_);                         \
            fma2(a23, w_, v1_);                         \
        } while (0)
        #define SAMP_P(RW, CW, ADDR, FLAG) do {         \
            unsigned long long v0_, v1_;                \
            lds128_pred(v0_, v1_, (ADDR), (FLAG));      \
            unsigned long long w_ = mul2((RW), (CW));   \
            fma2(a01, w_, v0_);                         \
            fma2(a23, w_, v1_);                         \
        } while (0)

        SAMP(wy0, wx0, r0 + c0);
        SAMP(wy0, wx1, r0 + c1);
        SAMP(wy1, wx0, r1 + c0);
        SAMP(wy1, wx1, r1 + c1);
        SAMP_P(wy0, wx2, r0 + c2, fx2);
        SAMP_P(wy1, wx2, r1 + c2, fx2);
        SAMP_P(wy2, wx0, r2 + c0, fy2);
        SAMP_P(wy2, wx1, r2 + c1, fy2);
        SAMP_P(wy2, wx2, r2 + c2, fxy);
        #undef SAMP
        #undef SAMP_P

        ulonglong2 o; o.x = a01; o.y = a23;
        out2[roi * (TOTAL_BINS * ALPHA / 4) + bin * (ALPHA / 4) + q] = o;
    }
}

extern "C" void kernel_launch(void* const* d_in, const int* in_sizes, int n_in,
                              void* d_out, int out_size)
{
    const float* p0 = (const float*)d_in[0];
    const float* p1 = (const float*)d_in[1];
    const float* img  = p0;
    const float* rois = p1;
    int rois_elems = in_sizes[1];
    if (in_sizes[0] < in_sizes[1]) {
        img = p1; rois = p0; rois_elems = in_sizes[0];
    }
    const int R = rois_elems / 4;      // 8192

    {
        int total = R * POOLN;
        int blocks = (total + 255) / 256;
        psroi_setup_kernel<<<blocks, 256>>>((const float4*)rois, R);
    }

    cudaFuncSetAttribute(psroi_main_kernel,
                         cudaFuncAttributeMaxDynamicSharedMemorySize, SMEM_BYTES);
    dim3 grid(TOTAL_BINS, R / ROIS_PER_BLOCK);     // 49 x 32 = 1568 blocks
    psroi_main_kernel<<<grid, THREADS, SMEM_BYTES>>>(
        (const float4*)img, (ulonglong2*)d_out);
}

// round 6
// speedup vs baseline: 1.5188x; 1.3683x over previous
#include <cuda_runtime.h>
#include <cstdint>

// PS-ROI Align, two-phase. Round-3 inner loop (branchless 9-tap f32x2,
// LDG+STS staging, no predication, no cp.async) with ROIS_PER_BLOCK=512
// (round-2-proven grid 49x16) and 0.25 folded into the weight tables.

namespace {
constexpr int POOLN       = 7;
constexpr int TOTAL_BINS  = 49;
constexpr int ALPHA       = 32;
constexpr int HH          = 20;
constexpr int WW          = 20;
constexpr int THREADS     = 256;
constexpr int GROUPS      = THREADS / 8;        // 32 rois per iter
constexpr int ROIS_PER_BLOCK = 512;
constexpr int MAX_ROIS    = 8192;
constexpr int SMEM_F4     = HH * WW * (ALPHA / 4);  // 3200 float4
constexpr int SMEM_BYTES  = SMEM_F4 * 16;           // 51200 B
}

// .x = bitcast int: i0 | i1<<8 | i2<<16 (clamped indices); .y/.z/.w = W0,W1,W2
// Weights pre-scaled by 0.5 per axis (product = the 0.25 mean factor).
__device__ float4 g_TX[MAX_ROIS * POOLN];
__device__ float4 g_TY[MAX_ROIS * POOLN];

__device__ __forceinline__ float4 axis_record(float origin, float step, int pos)
{
    const float sc = 19.0f / 20.0f;
    float c1 = (origin + (float)pos * step) * sc;
    float c2 = (origin + (float)(pos + 1) * step) * sc;

    float f1 = floorf(c1), f2 = floorf(c2);
    float w1 = c1 - f1,    w2 = c2 - f2;
    float v1 = (c1 >= 0.0f && c1 <= 19.0f) ? 1.0f : 0.0f;
    float v2 = (c2 >= 0.0f && c2 <= 19.0f) ? 1.0f : 0.0f;

    int a1 = min(max((int)f1, 0), 19);
    int b1 = min(a1 + 1, 19);
    int a2 = min(max((int)f2, 0), 19);
    int b2 = min(a2 + 1, 19);

    int o1 = b1 - a1;
    int o2 = min(max(a2 - a1, 0), 2);
    int o3 = min(max(b2 - a1, 0), 2);

    float u1 = v1 - v1 * w1;
    float u2 = v1 * w1;
    float u3 = v2 - v2 * w2;
    float u4 = v2 * w2;

    float W0 = u1 + (o1 == 0 ? u2 : 0.0f) + (o2 == 0 ? u3 : 0.0f) + (o3 == 0 ? u4 : 0.0f);
    float W1 =      (o1 == 1 ? u2 : 0.0f) + (o2 == 1 ? u3 : 0.0f) + (o3 == 1 ? u4 : 0.0f);
    float W2 =                              (o2 == 2 ? u3 : 0.0f) + (o3 == 2 ? u4 : 0.0f);

    int i0 = a1;
    int i1 = min(a1 + 1, 19);
    int i2 = min(a1 + 2, 19);

    float4 rec;
    rec.x = __int_as_float(i0 | (i1 << 8) | (i2 << 16));
    rec.y = 0.5f * W0; rec.z = 0.5f * W1; rec.w = 0.5f * W2;
    return rec;
}

__global__ void psroi_setup_kernel(const float4* __restrict__ rois4, int R)
{
    int idx = blockIdx.x * blockDim.x + threadIdx.x;   // roi*7 + pos
    if (idx >= R * POOLN) return;
    int roi = idx / POOLN;
    int pos = idx - roi * POOLN;
    float4 r = __ldg(&rois4[roi]);
    g_TX[idx] = axis_record(r.x, r.z * (1.0f / 7.0f), pos);
    g_TY[idx] = axis_record(r.y, r.w * (1.0f / 7.0f), pos);
}

// ---- packed f32x2 helpers ----
__device__ __forceinline__ unsigned long long pack2(float a) {
    unsigned long long r;
    asm("mov.b64 %0, {%1, %1};" : "=l"(r) : "f"(a));
    return r;
}
__device__ __forceinline__ unsigned long long mul2(unsigned long long a,
                                                   unsigned long long b) {
    unsigned long long r;
    asm("mul.rn.f32x2 %0, %1, %2;" : "=l"(r) : "l"(a), "l"(b));
    return r;
}
__device__ __forceinline__ void fma2(unsigned long long& d,
                                     unsigned long long a,
                                     unsigned long long b) {
    asm("fma.rn.f32x2 %0, %1, %2, %0;" : "+l"(d) : "l"(a), "l"(b));
}
__device__ __forceinline__ void lds128(unsigned long long& v0,
                                       unsigned long long& v1,
                                       uint32_t addr) {
    asm("ld.shared.v2.b64 {%0, %1}, [%2];" : "=l"(v0), "=l"(v1) : "r"(addr));
}

__global__ __launch_bounds__(THREADS, 4)
void psroi_main_kernel(const float4* __restrict__ img4,
                       ulonglong2* __restrict__ out2)
{
    extern __shared__ float4 s4[];     // [pix = y*20+x][aq 0..7]

    const int bin = blockIdx.x;        // 0..48
    const int bx  = bin / POOLN;
    const int by  = bin % POOLN;

    {   // stage this bin's slice (51.2KB) into SMEM (plain LDG+STS)
        const int binoff4 = bin * (ALPHA / 4);
        #pragma unroll 4
        for (int p = threadIdx.x; p < SMEM_F4; p += THREADS) {
            int pix = p >> 3;
            int aq  = p & 7;
            s4[p] = img4[pix * (TOTAL_BINS * ALPHA / 4) + binoff4 + aq];
        }
    }
    __syncthreads();

    const int grp = threadIdx.x >> 3;
    const int q   = threadIdx.x & 7;
    const int roi_base = blockIdx.y * ROIS_PER_BLOCK;

    const uint32_t sbase =
        (uint32_t)__cvta_generic_to_shared(s4) + (uint32_t)(q * 16);

    int txi = (roi_base + grp) * POOLN + bx;
    int tyi = (roi_base + grp) * POOLN + by;

    #pragma unroll 2
    for (int it = 0; it < ROIS_PER_BLOCK / GROUPS; ++it) {
        const int roi = roi_base + it * GROUPS + grp;
        const float4 wx = __ldg(&g_TX[txi]);
        const float4 wy = __ldg(&g_TY[tyi]);
        txi += GROUPS * POOLN;
        tyi += GROUPS * POOLN;

        const uint32_t px = (uint32_t)__float_as_int(wx.x);
        const uint32_t py = (uint32_t)__float_as_int(wy.x);
        // column byte offsets: x*32*4B = x<<7 ; row byte offsets: y*20*128
        const uint32_t c0 = sbase + ((px & 255u) << 7);
        const uint32_t c1 = sbase + (((px >> 8) & 255u) << 7);
        const uint32_t c2 = sbase + (((px >> 16) & 255u) << 7);
        const uint32_t r0 = (py & 255u) * 2560u;
        const uint32_t r1 = ((py >> 8) & 255u) * 2560u;
        const uint32_t r2 = ((py >> 16) & 255u) * 2560u;

        const unsigned long long wx0 = pack2(wx.y);
        const unsigned long long wx1 = pack2(wx.z);
        const unsigned long long wx2 = pack2(wx.w);
        const unsigned long long wy0 = pack2(wy.y);
        const unsigned long long wy1 = pack2(wy.z);
        const unsigned long long wy2 = pack2(wy.w);

        unsigned long long a01 = 0ull, a23 = 0ull;

        #define SAMP(RW, CW, ADDR) do {                 \
            unsigned long long v0_, v1_;                \
            lds128(v0_, v1_, (ADDR));                   \
            unsigned long long w_ = mul2((RW), (CW));   \
            fma2(a01, w_, v0_);                         \
            fma2(a23, w_, v1_);                         \
        } while (0)

        SAMP(wy0, wx0, r0 + c0);
        SAMP(wy0, wx1, r0 + c1);
        SAMP(wy0, wx2, r0 + c2);
        SAMP(wy1, wx0, r1 + c0);
        SAMP(wy1, wx1, r1 + c1);
        SAMP(wy1, wx2, r1 + c2);
        SAMP(wy2, wx0, r2 + c0);
        SAMP(wy2, wx1, r2 + c1);
        SAMP(wy2, wx2, r2 + c2);
        #undef SAMP

        ulonglong2 o; o.x = a01; o.y = a23;
        out2[roi * (TOTAL_BINS * ALPHA / 4) + bin * (ALPHA / 4) + q] = o;
    }
}

extern "C" void kernel_launch(void* const* d_in, const int* in_sizes, int n_in,
                              void* d_out, int out_size)
{
    const float* p0 = (const float*)d_in[0];
    const float* p1 = (const float*)d_in[1];
    const float* img  = p0;
    const float* rois = p1;
    int rois_elems = in_sizes[1];
    if (in_sizes[0] < in_sizes[1]) {
        img = p1; rois = p0; rois_elems = in_sizes[0];
    }
    const int R = rois_elems / 4;      // 8192

    {
        int total = R * POOLN;
        int blocks = (total + 255) / 256;
        psroi_setup_kernel<<<blocks, 256>>>((const float4*)rois, R);
    }

    cudaFuncSetAttribute(psroi_main_kernel,
                         cudaFuncAttributeMaxDynamicSharedMemorySize, SMEM_BYTES);
    dim3 grid(TOTAL_BINS, R / ROIS_PER_BLOCK);     // 49 x 16 = 784 blocks
    psroi_main_kernel<<<grid, THREADS, SMEM_BYTES>>>(
        (const float4*)img, (ulonglong2*)d_out);
}

// round 7
// speedup vs baseline: 1.6228x; 1.0685x over previous
#include <cuda_runtime.h>
#include <cstdint>

// PS-ROI Align, two-phase. Round-6 branchless 9-tap f32x2 inner loop,
// single-wave grid (49 x 12 = 588 blocks, all resident at occ 4), explicit
// table-LDG prefetch rotation. No predication, no cp.async (both proven
// regressions). Weights pre-scaled by 0.5/axis (0.25 mean factor folded in).

namespace {
constexpr int POOLN       = 7;
constexpr int TOTAL_BINS  = 49;
constexpr int ALPHA       = 32;
constexpr int HH          = 20;
constexpr int WW          = 20;
constexpr int THREADS     = 256;
constexpr int GROUPS      = THREADS / 8;        // 32 rois per iter
constexpr int CHUNKS      = 12;                 // 49*12 = 588 blocks = 1 wave
constexpr int MAX_ROIS    = 8192;
constexpr int SMEM_F4     = HH * WW * (ALPHA / 4);  // 3200 float4
constexpr int SMEM_BYTES  = SMEM_F4 * 16;           // 51200 B
}

// .x = bitcast int: i0 | i1<<8 | i2<<16 (clamped indices); .y/.z/.w = W0,W1,W2
__device__ float4 g_TX[MAX_ROIS * POOLN];
__device__ float4 g_TY[MAX_ROIS * POOLN];

__device__ __forceinline__ float4 axis_record(float origin, float step, int pos)
{
    const float sc = 19.0f / 20.0f;
    float c1 = (origin + (float)pos * step) * sc;
    float c2 = (origin + (float)(pos + 1) * step) * sc;

    float f1 = floorf(c1), f2 = floorf(c2);
    float w1 = c1 - f1,    w2 = c2 - f2;
    float v1 = (c1 >= 0.0f && c1 <= 19.0f) ? 1.0f : 0.0f;
    float v2 = (c2 >= 0.0f && c2 <= 19.0f) ? 1.0f : 0.0f;

    int a1 = min(max((int)f1, 0), 19);
    int b1 = min(a1 + 1, 19);
    int a2 = min(max((int)f2, 0), 19);
    int b2 = min(a2 + 1, 19);

    int o1 = b1 - a1;
    int o2 = min(max(a2 - a1, 0), 2);
    int o3 = min(max(b2 - a1, 0), 2);

    float u1 = v1 - v1 * w1;
    float u2 = v1 * w1;
    float u3 = v2 - v2 * w2;
    float u4 = v2 * w2;

    float W0 = u1 + (o1 == 0 ? u2 : 0.0f) + (o2 == 0 ? u3 : 0.0f) + (o3 == 0 ? u4 : 0.0f);
    float W1 =      (o1 == 1 ? u2 : 0.0f) + (o2 == 1 ? u3 : 0.0f) + (o3 == 1 ? u4 : 0.0f);
    float W2 =                              (o2 == 2 ? u3 : 0.0f) + (o3 == 2 ? u4 : 0.0f);

    int i0 = a1;
    int i1 = min(a1 + 1, 19);
    int i2 = min(a1 + 2, 19);

    float4 rec;
    rec.x = __int_as_float(i0 | (i1 << 8) | (i2 << 16));
    rec.y = 0.5f * W0; rec.z = 0.5f * W1; rec.w = 0.5f * W2;
    return rec;
}

__global__ void psroi_setup_kernel(const float4* __restrict__ rois4, int R)
{
    int idx = blockIdx.x * blockDim.x + threadIdx.x;   // roi*7 + pos
    if (idx >= R * POOLN) return;
    int roi = idx / POOLN;
    int pos = idx - roi * POOLN;
    float4 r = __ldg(&rois4[roi]);
    g_TX[idx] = axis_record(r.x, r.z * (1.0f / 7.0f), pos);
    g_TY[idx] = axis_record(r.y, r.w * (1.0f / 7.0f), pos);
}

// ---- packed f32x2 helpers ----
__device__ __forceinline__ unsigned long long pack2(float a) {
    unsigned long long r;
    asm("mov.b64 %0, {%1, %1};" : "=l"(r) : "f"(a));
    return r;
}
__device__ __forceinline__ unsigned long long mul2(unsigned long long a,
                                                   unsigned long long b) {
    unsigned long long r;
    asm("mul.rn.f32x2 %0, %1, %2;" : "=l"(r) : "l"(a), "l"(b));
    return r;
}
__device__ __forceinline__ void fma2(unsigned long long& d,
                                     unsigned long long a,
                                     unsigned long long b) {
    asm("fma.rn.f32x2 %0, %1, %2, %0;" : "+l"(d) : "l"(a), "l"(b));
}
__device__ __forceinline__ void lds128(unsigned long long& v0,
                                       unsigned long long& v1,
                                       uint32_t addr) {
    asm("ld.shared.v2.b64 {%0, %1}, [%2];" : "=l"(v0), "=l"(v1) : "r"(addr));
}

__global__ __launch_bounds__(THREADS, 4)
void psroi_main_kernel(const float4* __restrict__ img4,
                       ulonglong2* __restrict__ out2,
                       int R)
{
    extern __shared__ float4 s4[];     // [pix = y*20+x][aq 0..7]

    const int bin = blockIdx.x;        // 0..48
    const int bx  = bin / POOLN;
    const int by  = bin % POOLN;

    {   // stage this bin's slice (51.2KB) into SMEM (plain LDG+STS)
        const int binoff4 = bin * (ALPHA / 4);
        #pragma unroll 4
        for (int p = threadIdx.x; p < SMEM_F4; p += THREADS) {
            int pix = p >> 3;
            int aq  = p & 7;
            s4[p] = img4[pix * (TOTAL_BINS * ALPHA / 4) + binoff4 + aq];
        }
    }
    __syncthreads();

    const int grp = threadIdx.x >> 3;
    const int q   = threadIdx.x & 7;

    const int per_chunk = (R + CHUNKS - 1) / CHUNKS;     // 683
    const int roi_begin = blockIdx.y * per_chunk;
    const int roi_end   = min(roi_begin + per_chunk, R);
    const int iters     = (roi_end - roi_begin + GROUPS - 1) / GROUPS;

    const uint32_t sbase =
        (uint32_t)__cvta_generic_to_shared(s4) + (uint32_t)(q * 16);

    // prefetch first iteration's table records
    int roi_n = roi_begin + grp;
    int rc    = min(roi_n, roi_end - 1);
    float4 wxn = __ldg(&g_TX[rc * POOLN + bx]);
    float4 wyn = __ldg(&g_TY[rc * POOLN + by]);

    #pragma unroll 1
    for (int it = 0; it < iters; ++it) {
        const int roi = roi_n;
        const float4 wx = wxn;
        const float4 wy = wyn;

        // prefetch next iteration (clamped overread on the last iter: harmless)
        roi_n += GROUPS;
        rc = min(roi_n, roi_end - 1);
        wxn = __ldg(&g_TX[rc * POOLN + bx]);
        wyn = __ldg(&g_TY[rc * POOLN + by]);

        const uint32_t px = (uint32_t)__float_as_int(wx.x);
        const uint32_t py = (uint32_t)__float_as_int(wy.x);
        // column byte offsets: x*32*4B = x<<7 ; row byte offsets: y*20*128
        const uint32_t c0 = sbase + ((px & 255u) << 7);
        const uint32_t c1 = sbase + (((px >> 8) & 255u) << 7);
        const uint32_t c2 = sbase + (((px >> 16) & 255u) << 7);
        const uint32_t r0 = (py & 255u) * 2560u;
        const uint32_t r1 = ((py >> 8) & 255u) * 2560u;
        const uint32_t r2 = ((py >> 16) & 255u) * 2560u;

        const unsigned long long wx0 = pack2(wx.y);
        const unsigned long long wx1 = pack2(wx.z);
        const unsigned long long wx2 = pack2(wx.w);
        const unsigned long long wy0 = pack2(wy.y);
        const unsigned long long wy1 = pack2(wy.z);
        const unsigned long long wy2 = pack2(wy.w);

        unsigned long long a01 = 0ull, a23 = 0ull;

        #define SAMP(RW, CW, ADDR) do {                 \
            unsigned long long v0_, v1_;                \
            lds128(v0_, v1_, (ADDR));                   \
            unsigned long long w_ = mul2((RW), (CW));   \
            fma2(a01, w_, v0_);                         \
            fma2(a23, w_, v1_);                         \
        } while (0)

        SAMP(wy0, wx0, r0 + c0);
        SAMP(wy0, wx1, r0 + c1);
        SAMP(wy0, wx2, r0 + c2);
        SAMP(wy1, wx0, r1 + c0);
        SAMP(wy1, wx1, r1 + c1);
        SAMP(wy1, wx2, r1 + c2);
        SAMP(wy2, wx0, r2 + c0);
        SAMP(wy2, wx1, r2 + c1);
        SAMP(wy2, wx2, r2 + c2);
        #undef SAMP

        if (roi < roi_end) {
            ulonglong2 o; o.x = a01; o.y = a23;
            out2[roi * (TOTAL_BINS * ALPHA / 4) + bin * (ALPHA / 4) + q] = o;
        }
    }
}

extern "C" void kernel_launch(void* const* d_in, const int* in_sizes, int n_in,
                              void* d_out, int out_size)
{
    const float* p0 = (const float*)d_in[0];
    const float* p1 = (const float*)d_in[1];
    const float* img  = p0;
    const float* rois = p1;
    int rois_elems = in_sizes[1];
    if (in_sizes[0] < in_sizes[1]) {
        img = p1; rois = p0; rois_elems = in_sizes[0];
    }
    const int R = rois_elems / 4;      // 8192

    {
        int total = R * POOLN;
        int blocks = (total + 255) / 256;
        psroi_setup_kernel<<<blocks, 256>>>((const float4*)rois, R);
    }

    cudaFuncSetAttribute(psroi_main_kernel,
                         cudaFuncAttributeMaxDynamicSharedMemorySize, SMEM_BYTES);
    dim3 grid(TOTAL_BINS, CHUNKS);     // 49 x 12 = 588 blocks: single wave
    psroi_main_kernel<<<grid, THREADS, SMEM_BYTES>>>(
        (const float4*)img, (ulonglong2*)d_out, R);
}

// round 8
// speedup vs baseline: 1.6371x; 1.0088x over previous
#include <cuda_runtime.h>
#include <cstdint>

// PS-ROI Align, two-phase. R7 skeleton (single-wave 49x12 grid, table
// prefetch rotation, LDG+STS staging) with the inner reduction re-associated
// into per-row partial sums to cut the accumulator dependence chain from
// 9-deep to 3-deep (6 independent row-sum chains + 3-deep combine).

namespace {
constexpr int POOLN       = 7;
constexpr int TOTAL_BINS  = 49;
constexpr int ALPHA       = 32;
constexpr int HH          = 20;
constexpr int WW          = 20;
constexpr int THREADS     = 256;
constexpr int GROUPS      = THREADS / 8;        // 32 rois per iter
constexpr int CHUNKS      = 12;                 // 49*12 = 588 blocks = 1 wave
constexpr int MAX_ROIS    = 8192;
constexpr int SMEM_F4     = HH * WW * (ALPHA / 4);  // 3200 float4
constexpr int SMEM_BYTES  = SMEM_F4 * 16;           // 51200 B
}

// .x = bitcast int: i0 | i1<<8 | i2<<16 (clamped indices); .y/.z/.w = W0,W1,W2
// Weights pre-scaled by 0.5 per axis (product = the 0.25 mean factor).
__device__ float4 g_TX[MAX_ROIS * POOLN];
__device__ float4 g_TY[MAX_ROIS * POOLN];

__device__ __forceinline__ float4 axis_record(float origin, float step, int pos)
{
    const float sc = 19.0f / 20.0f;
    float c1 = (origin + (float)pos * step) * sc;
    float c2 = (origin + (float)(pos + 1) * step) * sc;

    float f1 = floorf(c1), f2 = floorf(c2);
    float w1 = c1 - f1,    w2 = c2 - f2;
    float v1 = (c1 >= 0.0f && c1 <= 19.0f) ? 1.0f : 0.0f;
    float v2 = (c2 >= 0.0f && c2 <= 19.0f) ? 1.0f : 0.0f;

    int a1 = min(max((int)f1, 0), 19);
    int b1 = min(a1 + 1, 19);
    int a2 = min(max((int)f2, 0), 19);
    int b2 = min(a2 + 1, 19);

    int o1 = b1 - a1;
    int o2 = min(max(a2 - a1, 0), 2);
    int o3 = min(max(b2 - a1, 0), 2);

    float u1 = v1 - v1 * w1;
    float u2 = v1 * w1;
    float u3 = v2 - v2 * w2;
    float u4 = v2 * w2;

    float W0 = u1 + (o1 == 0 ? u2 : 0.0f) + (o2 == 0 ? u3 : 0.0f) + (o3 == 0 ? u4 : 0.0f);
    float W1 =      (o1 == 1 ? u2 : 0.0f) + (o2 == 1 ? u3 : 0.0f) + (o3 == 1 ? u4 : 0.0f);
    float W2 =                              (o2 == 2 ? u3 : 0.0f) + (o3 == 2 ? u4 : 0.0f);

    int i0 = a1;
    int i1 = min(a1 + 1, 19);
    int i2 = min(a1 + 2, 19);

    float4 rec;
    rec.x = __int_as_float(i0 | (i1 << 8) | (i2 << 16));
    rec.y = 0.5f * W0; rec.z = 0.5f * W1; rec.w = 0.5f * W2;
    return rec;
}

__global__ void psroi_setup_kernel(const float4* __restrict__ rois4, int R)
{
    int idx = blockIdx.x * blockDim.x + threadIdx.x;   // roi*7 + pos
    if (idx >= R * POOLN) return;
    int roi = idx / POOLN;
    int pos = idx - roi * POOLN;
    float4 r = __ldg(&rois4[roi]);
    g_TX[idx] = axis_record(r.x, r.z * (1.0f / 7.0f), pos);
    g_TY[idx] = axis_record(r.y, r.w * (1.0f / 7.0f), pos);
}

// ---- packed f32x2 helpers ----
__device__ __forceinline__ unsigned long long pack2(float a) {
    unsigned long long r;
    asm("mov.b64 %0, {%1, %1};" : "=l"(r) : "f"(a));
    return r;
}
__device__ __forceinline__ unsigned long long mul2(unsigned long long a,
                                                   unsigned long long b) {
    unsigned long long r;
    asm("mul.rn.f32x2 %0, %1, %2;" : "=l"(r) : "l"(a), "l"(b));
    return r;
}
__device__ __forceinline__ void fma2(unsigned long long& d,
                                     unsigned long long a,
                                     unsigned long long b) {
    asm("fma.rn.f32x2 %0, %1, %2, %0;" : "+l"(d) : "l"(a), "l"(b));
}
__device__ __forceinline__ void lds128(unsigned long long& v0,
                                       unsigned long long& v1,
                                       uint32_t addr) {
    asm("ld.shared.v2.b64 {%0, %1}, [%2];" : "=l"(v0), "=l"(v1) : "r"(addr));
}

__global__ __launch_bounds__(THREADS, 4)
void psroi_main_kernel(const float4* __restrict__ img4,
                       ulonglong2* __restrict__ out2,
                       int R)
{
    extern __shared__ float4 s4[];     // [pix = y*20+x][aq 0..7]

    const int bin = blockIdx.x;        // 0..48
    const int bx  = bin / POOLN;
    const int by  = bin % POOLN;

    {   // stage this bin's slice (51.2KB) into SMEM (plain LDG+STS)
        const int binoff4 = bin * (ALPHA / 4);
        #pragma unroll 4
        for (int p = threadIdx.x; p < SMEM_F4; p += THREADS) {
            int pix = p >> 3;
            int aq  = p & 7;
            s4[p] = img4[pix * (TOTAL_BINS * ALPHA / 4) + binoff4 + aq];
        }
    }
    __syncthreads();

    const int grp = threadIdx.x >> 3;
    const int q   = threadIdx.x & 7;

    const int per_chunk = (R + CHUNKS - 1) / CHUNKS;     // 683
    const int roi_begin = blockIdx.y * per_chunk;
    const int roi_end   = min(roi_begin + per_chunk, R);
    const int iters     = (roi_end - roi_begin + GROUPS - 1) / GROUPS;

    const uint32_t sbase =
        (uint32_t)__cvta_generic_to_shared(s4) + (uint32_t)(q * 16);

    // prefetch first iteration's table records
    int roi_n = roi_begin + grp;
    int rc    = min(roi_n, roi_end - 1);
    float4 wxn = __ldg(&g_TX[rc * POOLN + bx]);
    float4 wyn = __ldg(&g_TY[rc * POOLN + by]);

    #pragma unroll 1
    for (int it = 0; it < iters; ++it) {
        const int roi = roi_n;
        const float4 wx = wxn;
        const float4 wy = wyn;

        // prefetch next iteration (clamped overread on the last iter: harmless)
        roi_n += GROUPS;
        rc = min(roi_n, roi_end - 1);
        wxn = __ldg(&g_TX[rc * POOLN + bx]);
        wyn = __ldg(&g_TY[rc * POOLN + by]);

        const uint32_t px = (uint32_t)__float_as_int(wx.x);
        const uint32_t py = (uint32_t)__float_as_int(wy.x);
        // column byte offsets: x*32*4B = x<<7 ; row byte offsets: y*20*128
        const uint32_t c0 = sbase + ((px & 255u) << 7);
        const uint32_t c1 = sbase + (((px >> 8) & 255u) << 7);
        const uint32_t c2 = sbase + (((px >> 16) & 255u) << 7);
        const uint32_t r0 = (py & 255u) * 2560u;
        const uint32_t r1 = ((py >> 8) & 255u) * 2560u;
        const uint32_t r2 = ((py >> 16) & 255u) * 2560u;

        const unsigned long long wx0 = pack2(wx.y);
        const unsigned long long wx1 = pack2(wx.z);
        const unsigned long long wx2 = pack2(wx.w);
        const unsigned long long wy0 = pack2(wy.y);
        const unsigned long long wy1 = pack2(wy.z);
        const unsigned long long wy2 = pack2(wy.w);

        // Row sums: u_r = wx0*v0 + wx1*v1 + wx2*v2 per half.
        // 6 independent 3-deep chains, then a 3-deep combine with wy.
        #define ROWSUM(UA, UB, RADDR) do {               \
            unsigned long long v0a_, v0b_, v1a_, v1b_, v2a_, v2b_; \
            lds128(v0a_, v0b_, (RADDR) + c0);            \
            lds128(v1a_, v1b_, (RADDR) + c1);            \
            lds128(v2a_, v2b_, (RADDR) + c2);            \
            UA = mul2(wx0, v0a_);                        \
            UB = mul2(wx0, v0b_);                        \
            fma2(UA, wx1, v1a_);                         \
            fma2(UB, wx1, v1b_);                         \
            fma2(UA, wx2, v2a_);                         \
            fma2(UB, wx2, v2b_);                         \
        } while (0)

        unsigned long long u0a, u0b, u1a, u1b, u2a, u2b;
        ROWSUM(u0a, u0b, r0);
        ROWSUM(u1a, u1b, r1);
        ROWSUM(u2a, u2b, r2);
        #undef ROWSUM

        unsigned long long a01 = mul2(wy0, u0a);
        unsigned long long a23 = mul2(wy0, u0b);
        fma2(a01, wy1, u1a);
        fma2(a23, wy1, u1b);
        fma2(a01, wy2, u2a);
        fma2(a23, wy2, u2b);

        if (roi < roi_end) {
            ulonglong2 o; o.x = a01; o.y = a23;
            out2[roi * (TOTAL_BINS * ALPHA / 4) + bin * (ALPHA / 4) + q] = o;
        }
    }
}

extern "C" void kernel_launch(void* const* d_in, const int* in_sizes, int n_in,
                              void* d_out, int out_size)
{
    const float* p0 = (const float*)d_in[0];
    const float* p1 = (const float*)d_in[1];
    const float* img  = p0;
    const float* rois = p1;
    int rois_elems = in_sizes[1];
    if (in_sizes[0] < in_sizes[1]) {
        img = p1; rois = p0; rois_elems = in_sizes[0];
    }
    const int R = rois_elems / 4;      // 8192

    {
        int total = R * POOLN;
        int blocks = (total + 255) / 256;
        psroi_setup_kernel<<<blocks, 256>>>((const float4*)rois, R);
    }

    cudaFuncSetAttribute(psroi_main_kernel,
                         cudaFuncAttributeMaxDynamicSharedMemorySize, SMEM_BYTES);
    dim3 grid(TOTAL_BINS, CHUNKS);     // 49 x 12 = 588 blocks: single wave
    psroi_main_kernel<<<grid, THREADS, SMEM_BYTES>>>(
        (const float4*)img, (ulonglong2*)d_out, R);
}

// round 9
// speedup vs baseline: 1.7462x; 1.0667x over previous
#include <cuda_runtime.h>
#include <cuda_fp16.h>
#include <cstdint>

// PS-ROI Align, two-phase. R7 skeleton (single-wave 49x12 grid, table
// prefetch, rowsum reduction) with the SMEM feature slice stored as fp16
// (halves the dominant LDS crossbar bytes; weights & accumulation stay fp32).

namespace {
constexpr int POOLN       = 7;
constexpr int TOTAL_BINS  = 49;
constexpr int ALPHA       = 32;
constexpr int HH          = 20;
constexpr int WW          = 20;
constexpr int THREADS     = 256;
constexpr int GROUPS      = THREADS / 8;        // 32 rois per iter
constexpr int CHUNKS      = 12;                 // 49*12 = 588 blocks = 1 wave
constexpr int MAX_ROIS    = 8192;
constexpr int SMEM_F4     = HH * WW * (ALPHA / 4);  // 3200 16B-fp32 = 8B-fp16 chunks
constexpr int SMEM_BYTES  = SMEM_F4 * 8;            // 25600 B (fp16)
}

// .x = bitcast int: i0 | i1<<8 | i2<<16 (clamped indices); .y/.z/.w = W0,W1,W2
// Weights pre-scaled by 0.5 per axis (product = the 0.25 mean factor).
__device__ float4 g_TX[MAX_ROIS * POOLN];
__device__ float4 g_TY[MAX_ROIS * POOLN];

__device__ __forceinline__ float4 axis_record(float origin, float step, int pos)
{
    const float sc = 19.0f / 20.0f;
    float c1 = (origin + (float)pos * step) * sc;
    float c2 = (origin + (float)(pos + 1) * step) * sc;

    float f1 = floorf(c1), f2 = floorf(c2);
    float w1 = c1 - f1,    w2 = c2 - f2;
    float v1 = (c1 >= 0.0f && c1 <= 19.0f) ? 1.0f : 0.0f;
    float v2 = (c2 >= 0.0f && c2 <= 19.0f) ? 1.0f : 0.0f;

    int a1 = min(max((int)f1, 0), 19);
    int b1 = min(a1 + 1, 19);
    int a2 = min(max((int)f2, 0), 19);
    int b2 = min(a2 + 1, 19);

    int o1 = b1 - a1;
    int o2 = min(max(a2 - a1, 0), 2);
    int o3 = min(max(b2 - a1, 0), 2);

    float u1 = v1 - v1 * w1;
    float u2 = v1 * w1;
    float u3 = v2 - v2 * w2;
    float u4 = v2 * w2;

    float W0 = u1 + (o1 == 0 ? u2 : 0.0f) + (o2 == 0 ? u3 : 0.0f) + (o3 == 0 ? u4 : 0.0f);
    float W1 =      (o1 == 1 ? u2 : 0.0f) + (o2 == 1 ? u3 : 0.0f) + (o3 == 1 ? u4 : 0.0f);
    float W2 =                              (o2 == 2 ? u3 : 0.0f) + (o3 == 2 ? u4 : 0.0f);

    int i0 = a1;
    int i1 = min(a1 + 1, 19);
    int i2 = min(a1 + 2, 19);

    float4 rec;
    rec.x = __int_as_float(i0 | (i1 << 8) | (i2 << 16));
    rec.y = 0.5f * W0; rec.z = 0.5f * W1; rec.w = 0.5f * W2;
    return rec;
}

__global__ void psroi_setup_kernel(const float4* __restrict__ rois4, int R)
{
    int idx = blockIdx.x * blockDim.x + threadIdx.x;   // roi*7 + pos
    if (idx >= R * POOLN) return;
    int roi = idx / POOLN;
    int pos = idx - roi * POOLN;
    float4 r = __ldg(&rois4[roi]);
    g_TX[idx] = axis_record(r.x, r.z * (1.0f / 7.0f), pos);
    g_TY[idx] = axis_record(r.y, r.w * (1.0f / 7.0f), pos);
}

// ---- packed f32x2 helpers ----
__device__ __forceinline__ unsigned long long pack2(float a) {
    unsigned long long r;
    asm("mov.b64 %0, {%1, %1};" : "=l"(r) : "f"(a));
    return r;
}
__device__ __forceinline__ unsigned long long packf2(float lo, float hi) {
    unsigned long long r;
    asm("mov.b64 %0, {%1, %2};" : "=l"(r) : "f"(lo), "f"(hi));
    return r;
}
__device__ __forceinline__ unsigned long long mul2(unsigned long long a,
                                                   unsigned long long b) {
    unsigned long long r;
    asm("mul.rn.f32x2 %0, %1, %2;" : "=l"(r) : "l"(a), "l"(b));
    return r;
}
__device__ __forceinline__ void fma2(unsigned long long& d,
                                     unsigned long long a,
                                     unsigned long long b) {
    asm("fma.rn.f32x2 %0, %1, %2, %0;" : "+l"(d) : "l"(a), "l"(b));
}
// 8B fp16 tap load (4 alphas) -> two f32x2 packed values
__device__ __forceinline__ void lds_h4(unsigned long long& v01,
                                       unsigned long long& v23,
                                       uint32_t addr) {
    uint32_t lo, hi;
    asm("ld.shared.v2.b32 {%0, %1}, [%2];" : "=r"(lo), "=r"(hi) : "r"(addr));
    __half2 h0 = *reinterpret_cast<__half2*>(&lo);
    __half2 h1 = *reinterpret_cast<__half2*>(&hi);
    float2 f0 = __half22float2(h0);
    float2 f1 = __half22float2(h1);
    v01 = packf2(f0.x, f0.y);
    v23 = packf2(f1.x, f1.y);
}

__global__ __launch_bounds__(THREADS, 4)
void psroi_main_kernel(const float4* __restrict__ img4,
                       ulonglong2* __restrict__ out2,
                       int R)
{
    extern __shared__ uint32_t sh[];   // fp16 slice: [pix = y*20+x][alpha 0..31]

    const int bin = blockIdx.x;        // 0..48
    const int bx  = bin / POOLN;
    const int by  = bin % POOLN;

    const uint32_t smem0 = (uint32_t)__cvta_generic_to_shared(sh);

    {   // stage this bin's slice, converting fp32 -> fp16 (25.6KB)
        const int binoff4 = bin * (ALPHA / 4);
        #pragma unroll 4
        for (int p = threadIdx.x; p < SMEM_F4; p += THREADS) {
            int pix = p >> 3;
            int aq  = p & 7;
            float4 v = img4[pix * (TOTAL_BINS * ALPHA / 4) + binoff4 + aq];
            __half2 h0 = __float22half2_rn(make_float2(v.x, v.y));
            __half2 h1 = __float22half2_rn(make_float2(v.z, v.w));
            uint32_t u0 = *reinterpret_cast<uint32_t*>(&h0);
            uint32_t u1 = *reinterpret_cast<uint32_t*>(&h1);
            asm volatile("st.shared.v2.b32 [%0], {%1, %2};"
                         :: "r"(smem0 + (uint32_t)p * 8u), "r"(u0), "r"(u1));
        }
    }
    __syncthreads();

    const int grp = threadIdx.x >> 3;
    const int q   = threadIdx.x & 7;

    const int per_chunk = (R + CHUNKS - 1) / CHUNKS;     // 683
    const int roi_begin = blockIdx.y * per_chunk;
    const int roi_end   = min(roi_begin + per_chunk, R);
    const int iters     = (roi_end - roi_begin + GROUPS - 1) / GROUPS;

    // fp16 layout: pixel chunk = 64B, q offset = q*8B
    const uint32_t sbase = smem0 + (uint32_t)(q * 8);

    // prefetch first iteration's table records
    int roi_n = roi_begin + grp;
    int rc    = min(roi_n, roi_end - 1);
    float4 wxn = __ldg(&g_TX[rc * POOLN + bx]);
    float4 wyn = __ldg(&g_TY[rc * POOLN + by]);

    #pragma unroll 1
    for (int it = 0; it < iters; ++it) {
        const int roi = roi_n;
        const float4 wx = wxn;
        const float4 wy = wyn;

        roi_n += GROUPS;
        rc = min(roi_n, roi_end - 1);
        wxn = __ldg(&g_TX[rc * POOLN + bx]);
        wyn = __ldg(&g_TY[rc * POOLN + by]);

        const uint32_t px = (uint32_t)__float_as_int(wx.x);
        const uint32_t py = (uint32_t)__float_as_int(wy.x);
        // column byte offsets: x*64 ; row byte offsets: y*20*64 = y*1280
        const uint32_t c0 = sbase + ((px & 255u) << 6);
        const uint32_t c1 = sbase + (((px >> 8) & 255u) << 6);
        const uint32_t c2 = sbase + (((px >> 16) & 255u) << 6);
        const uint32_t r0 = (py & 255u) * 1280u;
        const uint32_t r1 = ((py >> 8) & 255u) * 1280u;
        const uint32_t r2 = ((py >> 16) & 255u) * 1280u;

        const unsigned long long wx0 = pack2(wx.y);
        const unsigned long long wx1 = pack2(wx.z);
        const unsigned long long wx2 = pack2(wx.w);
        const unsigned long long wy0 = pack2(wy.y);
        const unsigned long long wy1 = pack2(wy.z);
        const unsigned long long wy2 = pack2(wy.w);

        // Row sums: u_r = wx0*v0 + wx1*v1 + wx2*v2 per alpha-pair half.
        #define ROWSUM(UA, UB, RADDR) do {               \
            unsigned long long v0a_, v0b_, v1a_, v1b_, v2a_, v2b_; \
            lds_h4(v0a_, v0b_, (RADDR) + c0);            \
            lds_h4(v1a_, v1b_, (RADDR) + c1);            \
            lds_h4(v2a_, v2b_, (RADDR) + c2);            \
            UA = mul2(wx0, v0a_);                        \
            UB = mul2(wx0, v0b_);                        \
            fma2(UA, wx1, v1a_);                         \
            fma2(UB, wx1, v1b_);                         \
            fma2(UA, wx2, v2a_);                         \
            fma2(UB, wx2, v2b_);                         \
        } while (0)

        unsigned long long u0a, u0b, u1a, u1b, u2a, u2b;
        ROWSUM(u0a, u0b, r0);
        ROWSUM(u1a, u1b, r1);
        ROWSUM(u2a, u2b, r2);
        #undef ROWSUM

        unsigned long long a01 = mul2(wy0, u0a);
        unsigned long long a23 = mul2(wy0, u0b);
        fma2(a01, wy1, u1a);
        fma2(a23, wy1, u1b);
        fma2(a01, wy2, u2a);
        fma2(a23, wy2, u2b);

        if (roi < roi_end) {
            ulonglong2 o; o.x = a01; o.y = a23;
            out2[roi * (TOTAL_BINS * ALPHA / 4) + bin * (ALPHA / 4) + q] = o;
        }
    }
}

extern "C" void kernel_launch(void* const* d_in, const int* in_sizes, int n_in,
                              void* d_out, int out_size)
{
    const float* p0 = (const float*)d_in[0];
    const float* p1 = (const float*)d_in[1];
    const float* img  = p0;
    const float* rois = p1;
    int rois_elems = in_sizes[1];
    if (in_sizes[0] < in_sizes[1]) {
        img = p1; rois = p0; rois_elems = in_sizes[0];
    }
    const int R = rois_elems / 4;      // 8192

    {
        int total = R * POOLN;
        int blocks = (total + 255) / 256;
        psroi_setup_kernel<<<blocks, 256>>>((const float4*)rois, R);
    }

    cudaFuncSetAttribute(psroi_main_kernel,
                         cudaFuncAttributeMaxDynamicSharedMemorySize, SMEM_BYTES);
    dim3 grid(TOTAL_BINS, CHUNKS);     // 49 x 12 = 588 blocks: single wave
    psroi_main_kernel<<<grid, THREADS, SMEM_BYTES>>>(
        (const float4*)img, (ulonglong2*)d_out, R);
}

// round 10
// speedup vs baseline: 1.9043x; 1.0906x over previous
#include <cuda_runtime.h>
#include <cuda_fp16.h>
#include <cstdint>

// PS-ROI Align, two-phase. R9 skeleton (fp16 SMEM slice, single-wave 49x12
// grid, table prefetch) with the x-axis row-sum done in fp16 via HFMA2:
// taps feed HFMA2 directly (no per-tap F2F), only the 6 row-sums convert to
// fp32 for the exact y-combine. Cuts 36 F2F/iter -> 12 and removes the
// 20-cycle F2F stage from every tap's dependence chain.

namespace {
constexpr int POOLN       = 7;
constexpr int TOTAL_BINS  = 49;
constexpr int ALPHA       = 32;
constexpr int HH          = 20;
constexpr int WW          = 20;
constexpr int THREADS     = 256;
constexpr int GROUPS      = THREADS / 8;        // 32 rois per iter
constexpr int CHUNKS      = 12;                 // 49*12 = 588 blocks = 1 wave
constexpr int MAX_ROIS    = 8192;
constexpr int SMEM_F4     = HH * WW * (ALPHA / 4);  // 3200 8B fp16 chunks
constexpr int SMEM_BYTES  = SMEM_F4 * 8;            // 25600 B
}

// .x = bitcast int: i0 | i1<<8 | i2<<16 (clamped indices); .y/.z/.w = W0,W1,W2
// Weights pre-scaled by 0.5 per axis (product = the 0.25 mean factor).
__device__ float4 g_TX[MAX_ROIS * POOLN];
__device__ float4 g_TY[MAX_ROIS * POOLN];

__device__ __forceinline__ float4 axis_record(float origin, float step, int pos)
{
    const float sc = 19.0f / 20.0f;
    float c1 = (origin + (float)pos * step) * sc;
    float c2 = (origin + (float)(pos + 1) * step) * sc;

    float f1 = floorf(c1), f2 = floorf(c2);
    float w1 = c1 - f1,    w2 = c2 - f2;
    float v1 = (c1 >= 0.0f && c1 <= 19.0f) ? 1.0f : 0.0f;
    float v2 = (c2 >= 0.0f && c2 <= 19.0f) ? 1.0f : 0.0f;

    int a1 = min(max((int)f1, 0), 19);
    int b1 = min(a1 + 1, 19);
    int a2 = min(max((int)f2, 0), 19);
    int b2 = min(a2 + 1, 19);

    int o1 = b1 - a1;
    int o2 = min(max(a2 - a1, 0), 2);
    int o3 = min(max(b2 - a1, 0), 2);

    float u1 = v1 - v1 * w1;
    float u2 = v1 * w1;
    float u3 = v2 - v2 * w2;
    float u4 = v2 * w2;

    float W0 = u1 + (o1 == 0 ? u2 : 0.0f) + (o2 == 0 ? u3 : 0.0f) + (o3 == 0 ? u4 : 0.0f);
    float W1 =      (o1 == 1 ? u2 : 0.0f) + (o2 == 1 ? u3 : 0.0f) + (o3 == 1 ? u4 : 0.0f);
    float W2 =                              (o2 == 2 ? u3 : 0.0f) + (o3 == 2 ? u4 : 0.0f);

    int i0 = a1;
    int i1 = min(a1 + 1, 19);
    int i2 = min(a1 + 2, 19);

    float4 rec;
    rec.x = __int_as_float(i0 | (i1 << 8) | (i2 << 16));
    rec.y = 0.5f * W0; rec.z = 0.5f * W1; rec.w = 0.5f * W2;
    return rec;
}

__global__ void psroi_setup_kernel(const float4* __restrict__ rois4, int R)
{
    int idx = blockIdx.x * blockDim.x + threadIdx.x;   // roi*7 + pos
    if (idx >= R * POOLN) return;
    int roi = idx / POOLN;
    int pos = idx - roi * POOLN;
    float4 r = __ldg(&rois4[roi]);
    g_TX[idx] = axis_record(r.x, r.z * (1.0f / 7.0f), pos);
    g_TY[idx] = axis_record(r.y, r.w * (1.0f / 7.0f), pos);
}

// ---- packed f32x2 helpers ----
__device__ __forceinline__ unsigned long long pack2(float a) {
    unsigned long long r;
    asm("mov.b64 %0, {%1, %1};" : "=l"(r) : "f"(a));
    return r;
}
__device__ __forceinline__ unsigned long long packf2(float lo, float hi) {
    unsigned long long r;
    asm("mov.b64 %0, {%1, %2};" : "=l"(r) : "f"(lo), "f"(hi));
    return r;
}
__device__ __forceinline__ unsigned long long mul2(unsigned long long a,
                                                   unsigned long long b) {
    unsigned long long r;
    asm("mul.rn.f32x2 %0, %1, %2;" : "=l"(r) : "l"(a), "l"(b));
    return r;
}
__device__ __forceinline__ void fma2(unsigned long long& d,
                                     unsigned long long a,
                                     unsigned long long b) {
    asm("fma.rn.f32x2 %0, %1, %2, %0;" : "+l"(d) : "l"(a), "l"(b));
}
// 8B fp16 tap load: 4 alphas as 2 x half2, no conversion.
__device__ __forceinline__ void lds_h2x2(__half2& h0, __half2& h1,
                                         uint32_t addr) {
    uint32_t lo, hi;
    asm("ld.shared.v2.b32 {%0, %1}, [%2];" : "=r"(lo), "=r"(hi) : "r"(addr));
    h0 = *reinterpret_cast<__half2*>(&lo);
    h1 = *reinterpret_cast<__half2*>(&hi);
}
__device__ __forceinline__ unsigned long long h2_to_f2(__half2 h) {
    float2 f = __half22float2(h);
    return packf2(f.x, f.y);
}

__global__ __launch_bounds__(THREADS, 4)
void psroi_main_kernel(const float4* __restrict__ img4,
                       ulonglong2* __restrict__ out2,
                       int R)
{
    extern __shared__ uint32_t sh[];   // fp16 slice: [pix = y*20+x][alpha 0..31]

    const int bin = blockIdx.x;        // 0..48
    const int bx  = bin / POOLN;
    const int by  = bin % POOLN;

    const uint32_t smem0 = (uint32_t)__cvta_generic_to_shared(sh);

    {   // stage this bin's slice, converting fp32 -> fp16 (25.6KB)
        const int binoff4 = bin * (ALPHA / 4);
        #pragma unroll 4
        for (int p = threadIdx.x; p < SMEM_F4; p += THREADS) {
            int pix = p >> 3;
            int aq  = p & 7;
            float4 v = img4[pix * (TOTAL_BINS * ALPHA / 4) + binoff4 + aq];
            __half2 h0 = __float22half2_rn(make_float2(v.x, v.y));
            __half2 h1 = __float22half2_rn(make_float2(v.z, v.w));
            uint32_t u0 = *reinterpret_cast<uint32_t*>(&h0);
            uint32_t u1 = *reinterpret_cast<uint32_t*>(&h1);
            asm volatile("st.shared.v2.b32 [%0], {%1, %2};"
                         :: "r"(smem0 + (uint32_t)p * 8u), "r"(u0), "r"(u1));
        }
    }
    __syncthreads();

    const int grp = threadIdx.x >> 3;
    const int q   = threadIdx.x & 7;

    const int per_chunk = (R + CHUNKS - 1) / CHUNKS;     // 683
    const int roi_begin = blockIdx.y * per_chunk;
    const int roi_end   = min(roi_begin + per_chunk, R);
    const int iters     = (roi_end - roi_begin + GROUPS - 1) / GROUPS;

    // fp16 layout: pixel chunk = 64B, q offset = q*8B
    const uint32_t sbase = smem0 + (uint32_t)(q * 8);

    // prefetch first iteration's table records
    int roi_n = roi_begin + grp;
    int rc    = min(roi_n, roi_end - 1);
    float4 wxn = __ldg(&g_TX[rc * POOLN + bx]);
    float4 wyn = __ldg(&g_TY[rc * POOLN + by]);

    #pragma unroll 1
    for (int it = 0; it < iters; ++it) {
        const int roi = roi_n;
        const float4 wx = wxn;
        const float4 wy = wyn;

        roi_n += GROUPS;
        rc = min(roi_n, roi_end - 1);
        wxn = __ldg(&g_TX[rc * POOLN + bx]);
        wyn = __ldg(&g_TY[rc * POOLN + by]);

        const uint32_t px = (uint32_t)__float_as_int(wx.x);
        const uint32_t py = (uint32_t)__float_as_int(wy.x);
        // column byte offsets: x*64 ; row byte offsets: y*20*64 = y*1280
        const uint32_t c0 = sbase + ((px & 255u) << 6);
        const uint32_t c1 = sbase + (((px >> 8) & 255u) << 6);
        const uint32_t c2 = sbase + (((px >> 16) & 255u) << 6);
        const uint32_t r0 = (py & 255u) * 1280u;
        const uint32_t r1 = ((py >> 8) & 255u) * 1280u;
        const uint32_t r2 = ((py >> 16) & 255u) * 1280u;

        // x-weights in fp16 (one conversion per iter, not per tap)
        const __half2 wx0h = __float2half2_rn(wx.y);
        const __half2 wx1h = __float2half2_rn(wx.z);
        const __half2 wx2h = __float2half2_rn(wx.w);
        // y-weights stay exact fp32
        const unsigned long long wy0 = pack2(wy.y);
        const unsigned long long wy1 = pack2(wy.z);
        const unsigned long long wy2 = pack2(wy.w);

        // Row sums in fp16: u_r = wx0*v0 + wx1*v1 + wx2*v2 per half2.
        #define ROWSUM_H(UA, UB, RADDR) do {             \
            __half2 v0a_, v0b_, v1a_, v1b_, v2a_, v2b_;  \
            lds_h2x2(v0a_, v0b_, (RADDR) + c0);          \
            lds_h2x2(v1a_, v1b_, (RADDR) + c1);          \
            lds_h2x2(v2a_, v2b_, (RADDR) + c2);          \
            UA = __hmul2(wx0h, v0a_);                    \
            UB = __hmul2(wx0h, v0b_);                    \
            UA = __hfma2(wx1h, v1a_, UA);                \
            UB = __hfma2(wx1h, v1b_, UB);                \
            UA = __hfma2(wx2h, v2a_, UA);                \
            UB = __hfma2(wx2h, v2b_, UB);                \
        } while (0)

        __half2 u0a, u0b, u1a, u1b, u2a, u2b;
        ROWSUM_H(u0a, u0b, r0);
        ROWSUM_H(u1a, u1b, r1);
        ROWSUM_H(u2a, u2b, r2);
        #undef ROWSUM_H

        // Convert the 6 row-sums to fp32 and combine exactly with wy.
        unsigned long long a01 = mul2(wy0, h2_to_f2(u0a));
        unsigned long long a23 = mul2(wy0, h2_to_f2(u0b));
        fma2(a01, wy1, h2_to_f2(u1a));
        fma2(a23, wy1, h2_to_f2(u1b));
        fma2(a01, wy2, h2_to_f2(u2a));
        fma2(a23, wy2, h2_to_f2(u2b));

        if (roi < roi_end) {
            ulonglong2 o; o.x = a01; o.y = a23;
            out2[roi * (TOTAL_BINS * ALPHA / 4) + bin * (ALPHA / 4) + q] = o;
        }
    }
}

extern "C" void kernel_launch(void* const* d_in, const int* in_sizes, int n_in,
                              void* d_out, int out_size)
{
    const float* p0 = (const float*)d_in[0];
    const float* p1 = (const float*)d_in[1];
    const float* img  = p0;
    const float* rois = p1;
    int rois_elems = in_sizes[1];
    if (in_sizes[0] < in_sizes[1]) {
        img = p1; rois = p0; rois_elems = in_sizes[0];
    }
    const int R = rois_elems / 4;      // 8192

    {
        int total = R * POOLN;
        int blocks = (total + 255) / 256;
        psroi_setup_kernel<<<blocks, 256>>>((const float4*)rois, R);
    }

    cudaFuncSetAttribute(psroi_main_kernel,
                         cudaFuncAttributeMaxDynamicSharedMemorySize, SMEM_BYTES);
    dim3 grid(TOTAL_BINS, CHUNKS);     // 49 x 12 = 588 blocks: single wave
    psroi_main_kernel<<<grid, THREADS, SMEM_BYTES>>>(
        (const float4*)img, (ulonglong2*)d_out, R);
}